// round 1
// baseline (speedup 1.0000x reference)
#include <cuda_runtime.h>
#include <cuda_bf16.h>
#include <cstdint>

// Problem constants
#define N_BANDS    128
#define RESO       64
#define N_FRAMES   128
#define N_SAMPLES  32768
#define BATCH      16
#define N_ROWS     (BATCH * N_BANDS)     // 2048 softmax rows

// Intermediate frames buffer, layout [f][b*128+c]  (f-major, 2048 floats per frame)
__device__ float g_frames[N_FRAMES * N_ROWS];

// ---------------------------------------------------------------------------
// Packed f32x2 helpers
// ---------------------------------------------------------------------------
__device__ __forceinline__ unsigned long long pack_dup(float x) {
    unsigned long long r;
    unsigned int xi = __float_as_uint(x);
    asm("mov.b64 %0, {%1, %1};" : "=l"(r) : "r"(xi));
    return r;
}

__device__ __forceinline__ unsigned long long fma2(unsigned long long a,
                                                   unsigned long long b,
                                                   unsigned long long c) {
    unsigned long long d;
    asm("fma.rn.f32x2 %0, %1, %2, %3;" : "=l"(d) : "l"(a), "l"(b), "l"(c));
    return d;
}

// ---------------------------------------------------------------------------
// Kernel 1: frames[b,c,f] = sum_r softmax(x[b,c,:])[r] * resonance[r,f]
// 128 blocks x 256 threads; block handles 16 rows (row = b*128+c).
// ---------------------------------------------------------------------------
__global__ __launch_bounds__(256)
void frames_kernel(const float* __restrict__ x,
                   const float* __restrict__ reso) {
    __shared__ float res_s[RESO][N_FRAMES];   // 32 KB
    __shared__ float xs[16][RESO];            // 4 KB
    __shared__ float ps[16][RESO + 1];        // padded to kill bank conflicts

    const int tid = threadIdx.x;
    const int rowbase = blockIdx.x * 16;      // 16 rows per block

    // Stage resonance (64x128) into smem, coalesced.
    for (int idx = tid; idx < RESO * N_FRAMES; idx += 256)
        res_s[idx >> 7][idx & 127] = reso[idx];

    // Stage x rows (16 x 64), coalesced.
    {
        const float* xb = x + rowbase * RESO;
        for (int idx = tid; idx < 16 * RESO; idx += 256)
            xs[idx >> 6][idx & 63] = xb[idx];
    }
    __syncthreads();

    // Softmax: warp w handles rows 2w, 2w+1 (2 elems per lane).
    {
        const int w = tid >> 5;
        const int lane = tid & 31;
        #pragma unroll
        for (int rr = 0; rr < 2; ++rr) {
            const int row = w * 2 + rr;
            float v0 = xs[row][lane];
            float v1 = xs[row][lane + 32];
            float m = fmaxf(v0, v1);
            #pragma unroll
            for (int off = 16; off > 0; off >>= 1)
                m = fmaxf(m, __shfl_xor_sync(0xFFFFFFFFu, m, off));
            float e0 = __expf(v0 - m);
            float e1 = __expf(v1 - m);
            float s = e0 + e1;
            #pragma unroll
            for (int off = 16; off > 0; off >>= 1)
                s += __shfl_xor_sync(0xFFFFFFFFu, s, off);
            float inv = 1.0f / s;
            ps[row][lane]      = e0 * inv;
            ps[row][lane + 32] = e1 * inv;
        }
    }
    __syncthreads();

    // frames: thread handles one row, 8 frame outputs at stride 16.
    // row = tid & 15 (16 rows), f = (tid>>4) + 16*i  (i = 0..7).
    {
        const int row_l = tid & 15;
        const int f0 = tid >> 4;   // 0..15
        float acc[8];
        #pragma unroll
        for (int i = 0; i < 8; ++i) acc[i] = 0.0f;

        #pragma unroll 4
        for (int r = 0; r < RESO; ++r) {
            const float pv = ps[row_l][r];          // conflict-free (padded)
            #pragma unroll
            for (int i = 0; i < 8; ++i)
                acc[i] = fmaf(pv, res_s[r][f0 + 16 * i], acc[i]);
        }

        const int grow = rowbase + row_l;
        #pragma unroll
        for (int i = 0; i < 8; ++i)
            g_frames[(f0 + 16 * i) * N_ROWS + grow] = acc[i];
    }
}

// ---------------------------------------------------------------------------
// Kernel 2: out[b,s] = (1/128) * ((1-w)*dot(f_i0[b,:], fb[:,s]) +
//                                    w *dot(f_i1[b,:], fb[:,s]))
// 128 blocks x 256 threads. Block n covers samples [256n, 256n+256).
// Lower 128 threads use frame pair (n-1, n), upper use (n, n+1) (clamped).
// Pairs pre-interleaved in smem as float2 -> one broadcast LDS.64 + one
// fma.rn.f32x2 per (c, b).
// ---------------------------------------------------------------------------
__global__ __launch_bounds__(256)
void mix_kernel(const float* __restrict__ fb,
                float* __restrict__ out) {
    __shared__ float2 pairs[2][N_ROWS];   // 32 KB

    const int tid = threadIdx.x;
    const int n = blockIdx.x;

    // Build interleaved pair tables.
    {
        const int fm1 = (n > 0 ? n - 1 : 0) * N_ROWS;
        const int fmid = n * N_ROWS;
        const int fp1 = (n < N_FRAMES - 1 ? n + 1 : N_FRAMES - 1) * N_ROWS;
        for (int i = tid; i < N_ROWS; i += 256) {
            float a = g_frames[fm1 + i];
            float m = g_frames[fmid + i];
            float p = g_frames[fp1 + i];
            pairs[0][i] = make_float2(a, m);
            pairs[1][i] = make_float2(m, p);
        }
    }
    __syncthreads();

    const int s = n * 256 + tid;
    const int sel = tid >> 7;  // warp-uniform
    const unsigned long long* __restrict__ P =
        reinterpret_cast<const unsigned long long*>(&pairs[sel][0]);

    // Interp weight (exact replication of align_corners=False semantics)
    float pos = (s + 0.5f) * (1.0f / 256.0f) - 0.5f;
    pos = fminf(fmaxf(pos, 0.0f), 127.0f);
    const float w = pos - floorf(pos);

    unsigned long long acc[BATCH];
    #pragma unroll
    for (int b = 0; b < BATCH; ++b) acc[b] = 0ull;

    const float* __restrict__ fbp = fb + s;   // element c at fbp[c*N_SAMPLES]

    // Prologue prefetch of first 8 filter-bank values.
    float cur[8];
    #pragma unroll
    for (int i = 0; i < 8; ++i) cur[i] = fbp[i * N_SAMPLES];

    for (int cc = 0; cc < N_BANDS; cc += 8) {
        // Prefetch next chunk (wraps to c=0 on last iter; harmless L2 hit).
        const int pc = (cc + 8 < N_BANDS) ? cc + 8 : 0;
        float nxt[8];
        #pragma unroll
        for (int i = 0; i < 8; ++i) nxt[i] = fbp[(pc + i) * N_SAMPLES];

        #pragma unroll
        for (int i = 0; i < 8; ++i) {
            const unsigned long long fd = pack_dup(cur[i]);
            const unsigned long long* Pc = P + (cc + i);
            #pragma unroll
            for (int b = 0; b < BATCH; ++b)
                acc[b] = fma2(Pc[b * N_BANDS], fd, acc[b]);
        }

        #pragma unroll
        for (int i = 0; i < 8; ++i) cur[i] = nxt[i];
    }

    // Epilogue: apply interp weight + mean over bands, write out.
    #pragma unroll
    for (int b = 0; b < BATCH; ++b) {
        const float a0 = __uint_as_float((unsigned int)(acc[b] & 0xFFFFFFFFull));
        const float a1 = __uint_as_float((unsigned int)(acc[b] >> 32));
        const float v = fmaf(w, a1 - a0, a0) * (1.0f / 128.0f);
        out[b * N_SAMPLES + s] = v;
    }
}

// ---------------------------------------------------------------------------
extern "C" void kernel_launch(void* const* d_in, const int* in_sizes, int n_in,
                              void* d_out, int out_size) {
    const float* x = nullptr;      // (16,128,64)    = 131072
    const float* reso = nullptr;   // (64,128)       = 8192
    const float* fb = nullptr;     // (1,128,32768)  = 4194304
    for (int i = 0; i < n_in; ++i) {
        if (in_sizes[i] == BATCH * N_BANDS * RESO)      x = (const float*)d_in[i];
        else if (in_sizes[i] == RESO * N_FRAMES)        reso = (const float*)d_in[i];
        else if (in_sizes[i] == N_BANDS * N_SAMPLES)    fb = (const float*)d_in[i];
    }
    float* out = (float*)d_out;

    frames_kernel<<<N_ROWS / 16, 256>>>(x, reso);
    mix_kernel<<<N_SAMPLES / 256, 256>>>(fb, out);
}

// round 2
// speedup vs baseline: 1.0880x; 1.0880x over previous
#include <cuda_runtime.h>
#include <cuda_bf16.h>
#include <cstdint>

// Problem constants
#define N_BANDS    128
#define RESO       64
#define N_FRAMES   128
#define N_SAMPLES  32768
#define BATCH      16
#define N_ROWS     (BATCH * N_BANDS)     // 2048 rows (b*128 + c)

// Intermediate frames buffer, layout [f][b*128+c]
__device__ float g_frames[N_FRAMES * N_ROWS];

// ---------------------------------------------------------------------------
// Packed f32x2 helpers
// ---------------------------------------------------------------------------
__device__ __forceinline__ unsigned long long pack_dup(float x) {
    unsigned long long r;
    unsigned int xi = __float_as_uint(x);
    asm("mov.b64 %0, {%1, %1};" : "=l"(r) : "r"(xi));
    return r;
}

__device__ __forceinline__ unsigned long long fma2(unsigned long long a,
                                                   unsigned long long b,
                                                   unsigned long long c) {
    unsigned long long d;
    asm("fma.rn.f32x2 %0, %1, %2, %3;" : "=l"(d) : "l"(a), "l"(b), "l"(c));
    return d;
}

// ---------------------------------------------------------------------------
// Kernel 1: frames[f][row] = sum_r softmax(x[row,:])[r] * resonance[r,f]
// 128 blocks x 256 threads; block handles 16 rows.
// ---------------------------------------------------------------------------
__global__ __launch_bounds__(256)
void frames_kernel(const float* __restrict__ x,
                   const float* __restrict__ reso) {
    __shared__ float res_s[RESO][N_FRAMES];   // 32 KB
    __shared__ float xs[16][RESO];            // 4 KB
    __shared__ float ps[16][RESO + 1];        // padded

    const int tid = threadIdx.x;
    const int rowbase = blockIdx.x * 16;

    for (int idx = tid; idx < RESO * N_FRAMES; idx += 256)
        res_s[idx >> 7][idx & 127] = reso[idx];

    {
        const float* xb = x + rowbase * RESO;
        for (int idx = tid; idx < 16 * RESO; idx += 256)
            xs[idx >> 6][idx & 63] = xb[idx];
    }
    __syncthreads();

    {
        const int w = tid >> 5;
        const int lane = tid & 31;
        #pragma unroll
        for (int rr = 0; rr < 2; ++rr) {
            const int row = w * 2 + rr;
            float v0 = xs[row][lane];
            float v1 = xs[row][lane + 32];
            float m = fmaxf(v0, v1);
            #pragma unroll
            for (int off = 16; off > 0; off >>= 1)
                m = fmaxf(m, __shfl_xor_sync(0xFFFFFFFFu, m, off));
            float e0 = __expf(v0 - m);
            float e1 = __expf(v1 - m);
            float s = e0 + e1;
            #pragma unroll
            for (int off = 16; off > 0; off >>= 1)
                s += __shfl_xor_sync(0xFFFFFFFFu, s, off);
            float inv = 1.0f / s;
            ps[row][lane]      = e0 * inv;
            ps[row][lane + 32] = e1 * inv;
        }
    }
    __syncthreads();

    {
        const int row_l = tid & 15;
        const int f0 = tid >> 4;
        float acc[8];
        #pragma unroll
        for (int i = 0; i < 8; ++i) acc[i] = 0.0f;

        #pragma unroll 4
        for (int r = 0; r < RESO; ++r) {
            const float pv = ps[row_l][r];
            #pragma unroll
            for (int i = 0; i < 8; ++i)
                acc[i] = fmaf(pv, res_s[r][f0 + 16 * i], acc[i]);
        }

        const int grow = rowbase + row_l;
        #pragma unroll
        for (int i = 0; i < 8; ++i)
            g_frames[(f0 + 16 * i) * N_ROWS + grow] = acc[i];
    }
}

// ---------------------------------------------------------------------------
// Kernel 2: 256 blocks x 256 threads. Block n covers samples [128n, 128n+128).
// Within a 128-sample block the (i0, i1) frame pair is uniform:
//   i0 = (n==0) ? 0 : (n-1)>>1   (crossings at s = 127.5 + 256k)
// Thread layout: warp w = batch-group (batches 2w, 2w+1); lane = 4-sample col.
// Per band: 1 LDG.128 (fb, 4 samples) + 2 LDS.64 (pairs, broadcast)
//           + 4 dup movs + 8 fma.rn.f32x2.
// ---------------------------------------------------------------------------
__global__ __launch_bounds__(256)
void mix_kernel(const float* __restrict__ fb,
                float* __restrict__ out) {
    __shared__ float2 pairs[BATCH][N_BANDS];   // 16 KB: (f_i0, f_i1) per (b,c)

    const int tid = threadIdx.x;
    const int n = blockIdx.x;

    const int i0 = (n == 0) ? 0 : ((n - 1) >> 1);
    const int i1 = (i0 + 1 < N_FRAMES) ? i0 + 1 : N_FRAMES - 1;

    // Build pair table (row = b*128 + c).
    {
        const float* f0p = g_frames + i0 * N_ROWS;
        const float* f1p = g_frames + i1 * N_ROWS;
        #pragma unroll
        for (int k = 0; k < N_ROWS / 256; ++k) {
            const int i = tid + k * 256;
            pairs[i >> 7][i & 127] = make_float2(f0p[i], f1p[i]);
        }
    }
    __syncthreads();

    const int lane = tid & 31;              // sample column (4 samples each)
    const int bg   = tid >> 5;              // batch group 0..7  (== warp id)
    const int s0 = n * 128 + lane * 4;

    // Interp weights for the 4 samples (align_corners=False semantics).
    float w[4];
    #pragma unroll
    for (int j = 0; j < 4; ++j) {
        float pos = (float)(s0 + j) * (1.0f / 256.0f) + (0.5f / 256.0f - 0.5f);
        pos = fminf(fmaxf(pos, 0.0f), 127.0f);
        w[j] = pos - floorf(pos);
    }

    const unsigned long long* __restrict__ P0 =
        reinterpret_cast<const unsigned long long*>(&pairs[2 * bg][0]);
    const unsigned long long* __restrict__ P1 =
        reinterpret_cast<const unsigned long long*>(&pairs[2 * bg + 1][0]);

    const float4* __restrict__ fbp =
        reinterpret_cast<const float4*>(fb + s0);   // band c at fbp[c*8192]

    unsigned long long acc0[4], acc1[4];
    #pragma unroll
    for (int j = 0; j < 4; ++j) { acc0[j] = 0ull; acc1[j] = 0ull; }

    // Software pipeline: 4 bands per chunk, prefetch next chunk.
    float4 cur[4], nxt[4];
    #pragma unroll
    for (int i = 0; i < 4; ++i) cur[i] = fbp[i * (N_SAMPLES / 4)];

    #pragma unroll 1
    for (int cc = 0; cc < N_BANDS; cc += 4) {
        const int pc = (cc + 4 < N_BANDS) ? cc + 4 : 0;
        #pragma unroll
        for (int i = 0; i < 4; ++i)
            nxt[i] = fbp[(pc + i) * (N_SAMPLES / 4)];

        #pragma unroll
        for (int i = 0; i < 4; ++i) {
            const int c = cc + i;
            const unsigned long long p0 = P0[c];
            const unsigned long long p1 = P1[c];
            const unsigned long long d0 = pack_dup(cur[i].x);
            const unsigned long long d1 = pack_dup(cur[i].y);
            const unsigned long long d2 = pack_dup(cur[i].z);
            const unsigned long long d3 = pack_dup(cur[i].w);
            acc0[0] = fma2(p0, d0, acc0[0]);
            acc0[1] = fma2(p0, d1, acc0[1]);
            acc0[2] = fma2(p0, d2, acc0[2]);
            acc0[3] = fma2(p0, d3, acc0[3]);
            acc1[0] = fma2(p1, d0, acc1[0]);
            acc1[1] = fma2(p1, d1, acc1[1]);
            acc1[2] = fma2(p1, d2, acc1[2]);
            acc1[3] = fma2(p1, d3, acc1[3]);
        }

        #pragma unroll
        for (int i = 0; i < 4; ++i) cur[i] = nxt[i];
    }

    // Epilogue: interp + mean over bands; coalesced float4 stores.
    {
        float4 o;
        float* op0 = out + (2 * bg) * N_SAMPLES + s0;
        float* op1 = out + (2 * bg + 1) * N_SAMPLES + s0;
        float v[4];
        #pragma unroll
        for (int j = 0; j < 4; ++j) {
            const float a0 = __uint_as_float((unsigned int)(acc0[j] & 0xFFFFFFFFull));
            const float a1 = __uint_as_float((unsigned int)(acc0[j] >> 32));
            v[j] = fmaf(w[j], a1 - a0, a0) * (1.0f / 128.0f);
        }
        o = make_float4(v[0], v[1], v[2], v[3]);
        *reinterpret_cast<float4*>(op0) = o;
        #pragma unroll
        for (int j = 0; j < 4; ++j) {
            const float a0 = __uint_as_float((unsigned int)(acc1[j] & 0xFFFFFFFFull));
            const float a1 = __uint_as_float((unsigned int)(acc1[j] >> 32));
            v[j] = fmaf(w[j], a1 - a0, a0) * (1.0f / 128.0f);
        }
        o = make_float4(v[0], v[1], v[2], v[3]);
        *reinterpret_cast<float4*>(op1) = o;
    }
}

// ---------------------------------------------------------------------------
extern "C" void kernel_launch(void* const* d_in, const int* in_sizes, int n_in,
                              void* d_out, int out_size) {
    const float* x = nullptr;      // (16,128,64)    = 131072
    const float* reso = nullptr;   // (64,128)       = 8192
    const float* fb = nullptr;     // (1,128,32768)  = 4194304
    for (int i = 0; i < n_in; ++i) {
        if (in_sizes[i] == BATCH * N_BANDS * RESO)      x = (const float*)d_in[i];
        else if (in_sizes[i] == RESO * N_FRAMES)        reso = (const float*)d_in[i];
        else if (in_sizes[i] == N_BANDS * N_SAMPLES)    fb = (const float*)d_in[i];
    }
    float* out = (float*)d_out;

    frames_kernel<<<N_ROWS / 16, 256>>>(x, reso);
    mix_kernel<<<N_SAMPLES / 128, 256>>>(fb, out);
}